// round 15
// baseline (speedup 1.0000x reference)
#include <cuda_runtime.h>
#include <math.h>

#define N_ENT 100000
#define N_REL 64
#define EDIM  64
#define KN    32
#define BSZ   1024
#define SLOPE 0.2f

__device__ float g_scale[N_ENT];
__device__ __align__(16) float g_Rw[N_REL * EDIM];  // [r][f] rows

// ---- packed fp32x2 helpers ----
__device__ __forceinline__ unsigned long long fma2(unsigned long long a,
                                                   unsigned long long b,
                                                   unsigned long long c) {
    unsigned long long d;
    asm("fma.rn.f32x2 %0, %1, %2, %3;" : "=l"(d) : "l"(a), "l"(b), "l"(c));
    return d;
}
__device__ __forceinline__ unsigned long long pack2(float lo, float hi) {
    unsigned long long d;
    asm("mov.b64 %0, {%1, %2};" : "=l"(d) : "f"(lo), "f"(hi));
    return d;
}
__device__ __forceinline__ float2 unpack2(unsigned long long v) {
    float2 r;
    asm("mov.b64 {%0, %1}, %2;" : "=f"(r.x), "=f"(r.y) : "l"(v));
    return r;
}

// ---------------------------------------------------------------------------
// Prep: per-row E scale (782 blocks) + Rw slices (16 blocks, [r][f] out)
// ---------------------------------------------------------------------------
__global__ void prep_kernel(const float* __restrict__ E,
                            const float* __restrict__ R,
                            const float* __restrict__ att_w1) {
    const int tid = threadIdx.x;  // 256
    if (blockIdx.x < 782) {
        const int row  = blockIdx.x * 128 + (tid >> 1);
        const int part = tid & 1;
        if (row >= N_ENT) return;
        const float4* Ev = reinterpret_cast<const float4*>(E + row * 64) + part * 8;
        float ss = 0.f;
        #pragma unroll
        for (int i = 0; i < 8; i++) {
            float4 v = Ev[i];
            ss += v.x*v.x + v.y*v.y + v.z*v.z + v.w*v.w;
        }
        ss += __shfl_xor_sync(0xffffffffu, ss, 1, 2);
        if (part == 0) {
            float n = sqrtf(ss);
            g_scale[row] = (n > 1.0f) ? (1.0f / (n + 1e-7f)) : 1.0f;
        }
        return;
    }
    __shared__ __align__(16) float sRn[N_REL * EDIM];
    __shared__ float sScale[N_REL];
    const int slice = blockIdx.x - 782;
    for (int i = tid; i < N_REL * EDIM; i += 256) sRn[i] = R[i];
    __syncthreads();
    if (tid < N_REL) {
        const float4* rv = reinterpret_cast<const float4*>(sRn + tid * EDIM);
        float ss = 0.f;
        #pragma unroll
        for (int e4 = 0; e4 < 16; e4++) {
            float4 v = rv[e4];
            ss += v.x*v.x + v.y*v.y + v.z*v.z + v.w*v.w;
        }
        float n = sqrtf(ss);
        sScale[tid] = (n > 1.0f) ? (1.0f / (n + 1e-7f)) : 1.0f;
    }
    __syncthreads();
    for (int i = tid; i < N_REL * EDIM; i += 256) sRn[i] *= sScale[i >> 6];
    __syncthreads();
    {
        int i = slice * 256 + tid;       // g_Rw[r][f]
        int r = i >> 6, f = i & 63;
        const float4* w  = reinterpret_cast<const float4*>(att_w1 + f * 128 + 64);
        const float4* rn = reinterpret_cast<const float4*>(sRn + r * 64);
        float a0 = 0.f, a1 = 0.f;
        #pragma unroll
        for (int e4 = 0; e4 < 16; e4 += 2) {
            float4 rv = rn[e4],     wv = w[e4];
            float4 rw = rn[e4 + 1], ww = w[e4 + 1];
            a0 += rv.x*wv.x + rv.y*wv.y + rv.z*wv.z + rv.w*wv.w;
            a1 += rw.x*ww.x + rw.y*ww.y + rw.z*ww.z + rw.w*ww.w;
        }
        g_Rw[i] = a0 + a1;
    }
}

// ---------------------------------------------------------------------------
// Shared stage-7 body: task-per-lane-pair, 2-way feature split.
// Returns attention pre-activation (valid on fh==0 lanes).
// ---------------------------------------------------------------------------
__device__ __forceinline__ float stage7_task(const float* __restrict__ bh,
                                             int r, int fh,
                                             const float* __restrict__ sW2,
                                             const float* __restrict__ sw3) {
    const float4* rw = reinterpret_cast<const float4*>(g_Rw + r * 64) + fh * 8;
    unsigned long long hidp[16];
    #pragma unroll
    for (int m4 = 0; m4 < 8; m4++) {
        float4 rv = __ldg(&rw[m4]);
        int f = fh * 32 + m4 * 4;
        float h0 = fmaxf(bh[f]     + rv.x, 0.0f);
        float h1 = fmaxf(bh[f + 1] + rv.y, 0.0f);
        float h2 = fmaxf(bh[f + 2] + rv.z, 0.0f);
        float h3 = fmaxf(bh[f + 3] + rv.w, 0.0f);
        hidp[m4 * 2]     = pack2(h0, h1);
        hidp[m4 * 2 + 1] = pack2(h2, h3);
    }
    const ulonglong2* w2 = reinterpret_cast<const ulonglong2*>(sW2);
    float a = 0.0f;
    #pragma unroll
    for (int gb = 0; gb < 64; gb += 8) {
        float dp[8];
        #pragma unroll
        for (int u = 0; u < 8; u++) {
            const int g = gb + u;
            unsigned long long dpp = 0ull;
            #pragma unroll
            for (int j = 0; j < 8; j++) {
                ulonglong2 wv = w2[g * 16 + j * 2 + fh];
                dpp = fma2(wv.x, hidp[j * 2],     dpp);
                dpp = fma2(wv.y, hidp[j * 2 + 1], dpp);
            }
            float2 dd = unpack2(dpp);
            dp[u] = dd.x + dd.y;
        }
        #pragma unroll
        for (int u = 0; u < 8; u++)
            dp[u] += __shfl_xor_sync(0xffffffffu, dp[u], 1);
        #pragma unroll
        for (int u = 0; u < 8; u++)
            a += sw3[gb + u] * fmaxf(dp[u], 0.0f);
    }
    return a;
}

// ---------------------------------------------------------------------------
// Main: TWO blocks per batch element (even bid = hop-1/A, odd bid = hop-2/B),
// 128 threads, 8 blocks/SM. Grid 2048.
// ---------------------------------------------------------------------------
__global__ __launch_bounds__(128, 8) void kgan_main_kernel(
    const int*   __restrict__ entity_idx,
    const int*   __restrict__ adj_entity,
    const int*   __restrict__ adj_relation,
    const float* __restrict__ E,
    const float* __restrict__ att_w1,
    const float* __restrict__ att_w2,
    const float* __restrict__ att_w3,
    const float* __restrict__ wx_w,
    const float* __restrict__ wx_b,
    const float* __restrict__ wc_w,
    const float* __restrict__ wc_b,
    float*       __restrict__ out)
{
    __shared__ __align__(16) float sW2[64 * 64];    // permuted float4 slots: g*16 + j*2 + fh
    __shared__ __align__(16) int2  sPair[1024];     // B only: (ei|ri<<17, scale); partials reuse
    __shared__ float sw3[64];
    __shared__ float sx[64];                        // A: h,  B: hsum
    __shared__ float sbh[64];
    __shared__ int   sEnt1[32], sRel1[32];
    __shared__ float sScale1[32];
    __shared__ float sA[64];
    __shared__ float sWtab[64];                     // A: wk(32)+wks(32), B: e2(64)
    __shared__ float sDen[4];
    __shared__ float sAgg[64], sV[64];

    const int tid   = threadIdx.x;
    const int btype = blockIdx.x & 1;               // 0 = A (hop1), 1 = B (hop2)
    const int b     = blockIdx.x >> 1;
    const int lane  = tid & 31;
    const int warp  = tid >> 5;

    // ================= common setup ========================================
    {
        const float4* Ws = reinterpret_cast<const float4*>(att_w2);
        float4*       Wd = reinterpret_cast<float4*>(sW2);
        #pragma unroll
        for (int q = 0; q < 8; q++) {
            int i = tid + q * 128;
            int g = i >> 4, i4 = i & 15;
            Wd[g * 16 + ((i4 & 7) << 1) + (i4 >> 3)] = Ws[i];  // interleave f-halves
        }
    }
    if (tid < 64) sw3[tid] = att_w3[tid];
    const int eidx = entity_idx[b];
    if (tid < 32) {
        int e1 = adj_entity[eidx * KN + tid];
        sEnt1[tid]   = e1;
        sRel1[tid]   = adj_relation[eidx * KN + tid];
        sScale1[tid] = g_scale[e1];
    }
    if (btype == 0) {
        // ===================== BLOCK A: hop-1 path =========================
        if (tid < 64) sx[tid] = E[eidx * 64 + tid] * g_scale[eidx];  // h
        __syncthreads();

        // bh1 = h @ w1h^T
        if (tid < 64) {
            const float4* w = reinterpret_cast<const float4*>(att_w1 + tid * 128);
            float a0 = 0.f, a1 = 0.f;
            #pragma unroll
            for (int e4 = 0; e4 < 16; e4 += 2) {
                float4 wv = w[e4], ww = w[e4 + 1];
                a0 += wv.x * sx[e4*4]   + wv.y * sx[e4*4+1]
                    + wv.z * sx[e4*4+2] + wv.w * sx[e4*4+3];
                a1 += ww.x * sx[e4*4+4] + ww.y * sx[e4*4+5]
                    + ww.z * sx[e4*4+6] + ww.w * sx[e4*4+7];
            }
            sbh[tid] = a0 + a1;
        }
        __syncthreads();

        // stage 7: 32 tasks x 2 fh = 64 threads
        if (tid < 64) {
            int task = tid >> 1, fh = tid & 1;
            float a = stage7_task(sbh, sRel1[task], fh, sW2, sw3);
            if (fh == 0) sA[task] = a;
        }
        __syncthreads();

        if (tid < 32) {
            float e = __expf(1.0f / (1.0f + __expf(-sA[tid])));
            sWtab[tid]      = e;                  // wk
            sWtab[32 + tid] = e * sScale1[tid];   // wks
        }
        __syncthreads();

        // hop-1 aggregation
        if (tid < 64) {
            float s1 = 0.f, acc = 0.f;
            #pragma unroll
            for (int k = 0; k < 32; k++) s1 += sWtab[k];
            #pragma unroll 8
            for (int k = 0; k < 32; k++)
                acc += sWtab[32 + k] * E[sEnt1[k] * 64 + tid];
            sAgg[tid] = acc / s1;
        }
        __syncthreads();
    } else {
        // ===================== BLOCK B: hop-2 path =========================
        __syncthreads();   // sEnt1 ready

        // hsum (tid<64) | pair staging w/ scale (tid in [64,128), 16 each)
        if (tid < 64) {
            float s = 0.f;
            #pragma unroll 8
            for (int k = 0; k < 32; k++)
                s += sScale1[k] * E[sEnt1[k] * 64 + tid];
            sx[tid] = s;   // hsum
        } else {
            const int t = tid - 64;          // 0..63
            #pragma unroll
            for (int q = 0; q < 16; q++) {
                int p  = t + q * 64;
                int n1 = p >> 5, k = p & 31;
                int base = sEnt1[n1] * KN;
                int ei = adj_entity[base + k];
                int ri = adj_relation[base + k];
                sPair[p] = make_int2(ei | (ri << 17), __float_as_int(g_scale[ei]));
            }
        }
        __syncthreads();

        // bh2 = hsum @ w1h^T
        if (tid < 64) {
            const float4* w = reinterpret_cast<const float4*>(att_w1 + tid * 128);
            float a0 = 0.f, a1 = 0.f;
            #pragma unroll
            for (int e4 = 0; e4 < 16; e4 += 2) {
                float4 wv = w[e4], ww = w[e4 + 1];
                a0 += wv.x * sx[e4*4]   + wv.y * sx[e4*4+1]
                    + wv.z * sx[e4*4+2] + wv.w * sx[e4*4+3];
                a1 += ww.x * sx[e4*4+4] + ww.y * sx[e4*4+5]
                    + ww.z * sx[e4*4+6] + ww.w * sx[e4*4+7];
            }
            sbh[tid] = a0 + a1;
        }
        __syncthreads();

        // stage 7: 64 tasks x 2 fh = 128 threads, exact single pass
        {
            int task = tid >> 1, fh = tid & 1;
            float a = stage7_task(sbh, task, fh, sW2, sw3);
            if (fh == 0) sA[task] = a;
        }
        __syncthreads();

        if (tid < 64)
            sWtab[tid] = __expf(1.0f / (1.0f + __expf(-sA[tid])));   // e2
        __syncthreads();

        // gather: 4 warps x 256 pairs, fused weights + denominator
        {
            float accx = 0.f, accy = 0.f, esum = 0.f;
            const float2* E2 = reinterpret_cast<const float2*>(E);
            const int pbase = warp * 256;
            #pragma unroll 8
            for (int t = 0; t < 256; t++) {
                int2  pr = sPair[pbase + t];     // LDS.64 broadcast
                int   ri = pr.x >> 17;
                int  idx = pr.x & 0x1FFFF;
                float e  = sWtab[ri];
                esum    += e;
                float wt = e * __int_as_float(pr.y);
                float2 v = E2[idx * 32 + lane];
                accx += wt * v.x;
                accy += wt * v.y;
            }
            if (lane == 0) sDen[warp] = esum;    // all lanes identical
            sPair[pbase + lane] = make_int2(__float_as_int(accx), __float_as_int(accy));
        }
        __syncthreads();

        // combine
        if (tid < 64) {
            int l = tid >> 1, c = tid & 1;
            float s2 = sDen[0] + sDen[1] + sDen[2] + sDen[3];
            float acc = 0.f;
            #pragma unroll
            for (int w = 0; w < 4; w++) {
                int2 pr = sPair[w * 256 + l];
                acc += __int_as_float(c ? pr.y : pr.x);
            }
            sAgg[tid] = acc / s2;
        }
        __syncthreads();
    }

    // ====== v = leaky(agg @ wx_w^T + wx_b) (common) ========================
    if (tid < 64) {
        const float4* w = reinterpret_cast<const float4*>(wx_w + tid * 64);
        float a = wx_b[tid];
        #pragma unroll
        for (int e4 = 0; e4 < 16; e4++) {
            float4 wv = w[e4];
            a += wv.x * sAgg[e4*4]   + wv.y * sAgg[e4*4+1]
               + wv.z * sAgg[e4*4+2] + wv.w * sAgg[e4*4+3];
        }
        sV[tid] = (a >= 0.f) ? a : SLOPE * a;
    }
    __syncthreads();

    // ====== emb = leaky([x, v] @ wc_w^T + wc_b) (common) + outputs =========
    if (tid < 64) {
        const float4* w = reinterpret_cast<const float4*>(wc_w + tid * 128);
        float a = wc_b[tid];
        #pragma unroll
        for (int e4 = 0; e4 < 16; e4++) {
            float4 wv = w[e4];
            a += wv.x * sx[e4*4]   + wv.y * sx[e4*4+1]
               + wv.z * sx[e4*4+2] + wv.w * sx[e4*4+3];
        }
        #pragma unroll
        for (int e4 = 0; e4 < 16; e4++) {
            float4 wv = w[16 + e4];
            a += wv.x * sV[e4*4]   + wv.y * sV[e4*4+1]
               + wv.z * sV[e4*4+2] + wv.w * sV[e4*4+3];
        }
        float emb = (a >= 0.f) ? a : SLOPE * a;
        if (btype == 0) {
            out[b * 192 + 64 + tid]  = emb;      // emb1
            out[b * 192 + 128 + tid] = sx[tid];  // h
        } else {
            out[b * 192 + tid] = emb;            // emb2
        }
    }
}

extern "C" void kernel_launch(void* const* d_in, const int* in_sizes, int n_in,
                              void* d_out, int out_size) {
    const int*   entity_idx   = (const int*)  d_in[0];
    const int*   adj_entity   = (const int*)  d_in[1];
    const int*   adj_relation = (const int*)  d_in[2];
    const float* E            = (const float*)d_in[3];
    const float* R            = (const float*)d_in[4];
    const float* att_w1       = (const float*)d_in[5];
    const float* att_w2       = (const float*)d_in[6];
    const float* att_w3       = (const float*)d_in[7];
    const float* wx_w         = (const float*)d_in[8];
    const float* wx_b         = (const float*)d_in[9];
    const float* wc_w         = (const float*)d_in[10];
    const float* wc_b         = (const float*)d_in[11];
    float* out = (float*)d_out;

    prep_kernel<<<798, 256>>>(E, R, att_w1);
    kgan_main_kernel<<<BSZ * 2, 128>>>(entity_idx, adj_entity, adj_relation, E,
                                       att_w1, att_w2, att_w3,
                                       wx_w, wx_b, wc_w, wc_b, out);
}

// round 16
// speedup vs baseline: 1.2531x; 1.2531x over previous
#include <cuda_runtime.h>
#include <math.h>

#define N_ENT 100000
#define N_REL 64
#define EDIM  64
#define KN    32
#define BSZ   1024
#define SLOPE 0.2f

// Scratch (device globals; no allocation allowed)
__device__ float g_scale[N_ENT];                    // per-row normalization scale
__device__ __align__(16) float g_RwT[EDIM * N_REL]; // [f][r] = Rn[r]·att_w1[f][64:]

// ---- packed fp32x2 helpers (sm_103a FFMA2 only reachable via PTX) ----------
__device__ __forceinline__ unsigned long long fma2(unsigned long long a,
                                                   unsigned long long b,
                                                   unsigned long long c) {
    unsigned long long d;
    asm("fma.rn.f32x2 %0, %1, %2, %3;" : "=l"(d) : "l"(a), "l"(b), "l"(c));
    return d;
}
__device__ __forceinline__ unsigned long long pack2(float lo, float hi) {
    unsigned long long d;
    asm("mov.b64 %0, {%1, %2};" : "=l"(d) : "f"(lo), "f"(hi));
    return d;
}
__device__ __forceinline__ float2 unpack2(unsigned long long v) {
    float2 r;
    asm("mov.b64 {%0, %1}, %2;" : "=f"(r.x), "=f"(r.y) : "l"(v));
    return r;
}

// ---------------------------------------------------------------------------
// Prep: per-row E scale (782 blocks) + Rw slices (16 blocks, [f][r] out)
// ---------------------------------------------------------------------------
__global__ void prep_kernel(const float* __restrict__ E,
                            const float* __restrict__ R,
                            const float* __restrict__ att_w1) {
    const int tid = threadIdx.x;  // 256
    if (blockIdx.x < 782) {
        const int row  = blockIdx.x * 128 + (tid >> 1);
        const int part = tid & 1;
        if (row >= N_ENT) return;
        const float4* Ev = reinterpret_cast<const float4*>(E + row * 64) + part * 8;
        float ss = 0.f;
        #pragma unroll
        for (int i = 0; i < 8; i++) {
            float4 v = Ev[i];
            ss += v.x*v.x + v.y*v.y + v.z*v.z + v.w*v.w;
        }
        ss += __shfl_xor_sync(0xffffffffu, ss, 1, 2);
        if (part == 0) {
            float n = sqrtf(ss);
            g_scale[row] = (n > 1.0f) ? (1.0f / (n + 1e-7f)) : 1.0f;
        }
        return;
    }
    __shared__ __align__(16) float sRn[N_REL * EDIM];
    __shared__ float sScale[N_REL];
    const int slice = blockIdx.x - 782;
    for (int i = tid; i < N_REL * EDIM; i += 256) sRn[i] = R[i];
    __syncthreads();
    if (tid < N_REL) {
        const float4* rv = reinterpret_cast<const float4*>(sRn + tid * EDIM);
        float ss = 0.f;
        #pragma unroll
        for (int e4 = 0; e4 < 16; e4++) {
            float4 v = rv[e4];
            ss += v.x*v.x + v.y*v.y + v.z*v.z + v.w*v.w;
        }
        float n = sqrtf(ss);
        sScale[tid] = (n > 1.0f) ? (1.0f / (n + 1e-7f)) : 1.0f;
    }
    __syncthreads();
    for (int i = tid; i < N_REL * EDIM; i += 256) sRn[i] *= sScale[i >> 6];
    __syncthreads();
    {
        int i = slice * 256 + tid;       // output index into g_RwT[f][r]
        int f = i >> 6, r = i & 63;
        const float4* w  = reinterpret_cast<const float4*>(att_w1 + f * 128 + 64);
        const float4* rn = reinterpret_cast<const float4*>(sRn + r * 64);
        float a0 = 0.f, a1 = 0.f;
        #pragma unroll
        for (int e4 = 0; e4 < 16; e4 += 2) {
            float4 rv = rn[e4],     wv = w[e4];
            float4 rw = rn[e4 + 1], ww = w[e4 + 1];
            a0 += rv.x*wv.x + rv.y*wv.y + rv.z*wv.z + rv.w*wv.w;
            a1 += rw.x*ww.x + rw.y*ww.y + rw.z*ww.z + rw.w*ww.w;
        }
        g_RwT[i] = a0 + a1;
    }
}

// ---------------------------------------------------------------------------
// Main: one block per batch element, 128 threads, 8 blocks/SM.
// R7 structure; pair weights + softmax denominator fused into the gather.
// ---------------------------------------------------------------------------
__global__ __launch_bounds__(128, 8) void kgan_main_kernel(
    const int*   __restrict__ entity_idx,
    const int*   __restrict__ adj_entity,
    const int*   __restrict__ adj_relation,
    const float* __restrict__ E,
    const float* __restrict__ att_w1,
    const float* __restrict__ att_w2,
    const float* __restrict__ att_w3,
    const float* __restrict__ wx_w,
    const float* __restrict__ wx_b,
    const float* __restrict__ wc_w,
    const float* __restrict__ wc_b,
    float*       __restrict__ out)
{
    __shared__ __align__(16) float sW2[64 * 64];    // permuted float4 slots: g*16 + j*2 + fh
    __shared__ __align__(16) int2  sPair[1024];     // (ei|ri<<17, scale-bits); partials reuse
    __shared__ float sw3[64];
    __shared__ float sh[64], shsum[64], sbh1[64], sbh2[64];
    __shared__ int   sEnt1[32], sRel1[32];
    __shared__ float sScale1[32];
    __shared__ float sA[96];
    __shared__ float sWk[32], sWks[32], sE2[64];
    __shared__ float sDen[4];
    __shared__ float sAgg1[64], sAgg2[64], sV1[64], sV2[64];

    const int tid  = threadIdx.x;
    const int b    = blockIdx.x;
    const int lane = tid & 31;
    const int warp = tid >> 5;

    // ================= phase A: W2 table + level-1 indices =================
    {
        const float4* Ws = reinterpret_cast<const float4*>(att_w2);
        float4*       Wd = reinterpret_cast<float4*>(sW2);
        #pragma unroll
        for (int q = 0; q < 8; q++) {
            int i = tid + q * 128;
            int g = i >> 4, i4 = i & 15;
            Wd[g * 16 + ((i4 & 7) << 1) + (i4 >> 3)] = Ws[i];  // interleave f-halves
        }
    }
    if (tid < 64) sw3[tid] = att_w3[tid];
    const int eidx = entity_idx[b];
    if (tid < 32) {
        int e1 = adj_entity[eidx * KN + tid];
        sEnt1[tid]   = e1;
        sRel1[tid]   = adj_relation[eidx * KN + tid];
        sScale1[tid] = g_scale[e1];
    }
    if (tid < 64) sh[tid] = E[eidx * 64 + tid] * g_scale[eidx];
    __syncthreads();

    // ====== phase B: stage hop-2 pairs (ei|ri, scale) + hsum ===============
    #pragma unroll
    for (int q = 0; q < 8; q++) {
        int p  = tid + q * 128;
        int n1 = p >> 5, k = p & 31;
        int base = sEnt1[n1] * KN;
        int ei = adj_entity[base + k];
        int ri = adj_relation[base + k];
        sPair[p] = make_int2(ei | (ri << 17), __float_as_int(g_scale[ei]));
    }
    if (tid < 64) {
        float s = 0.f;
        #pragma unroll 8
        for (int k = 0; k < 32; k++)
            s += sScale1[k] * E[sEnt1[k] * 64 + tid];
        shsum[tid] = s;
    }
    __syncthreads();

    // ====== phase C: bh1 = h @ w1h^T, bh2 = hsum @ w1h^T (128 threads) =====
    {
        int f = tid & 63;
        const float*  src = (tid < 64) ? sh : shsum;
        const float4* w   = reinterpret_cast<const float4*>(att_w1 + f * 128);
        float a0 = 0.f, a1 = 0.f;
        #pragma unroll
        for (int e4 = 0; e4 < 16; e4 += 2) {
            float4 wv = w[e4], ww = w[e4 + 1];
            a0 += wv.x * src[e4*4]   + wv.y * src[e4*4+1]
                + wv.z * src[e4*4+2] + wv.w * src[e4*4+3];
            a1 += ww.x * src[e4*4+4] + ww.y * src[e4*4+5]
                + ww.z * src[e4*4+6] + ww.w * src[e4*4+7];
        }
        if (tid < 64) sbh1[f] = a0 + a1; else sbh2[f] = a0 + a1;
    }
    __syncthreads();

    // ====== stage 7: 96 tasks x 2 f-halves = 192 thread-tasks, 2 passes ====
    #pragma unroll
    for (int pass = 0; pass < 2; pass++) {
        int tt = tid + pass * 128;
        if (tt < 192) {
            const int task = tt >> 1;
            const int fh   = tt & 1;
            const float* bh = (task < 32) ? sbh1 : sbh2;
            const int    r  = (task < 32) ? sRel1[task] : (task - 32);

            unsigned long long hidp[16];
            #pragma unroll
            for (int m = 0; m < 16; m++) {
                int f = fh * 32 + m * 2;
                float h0 = fmaxf(bh[f]     + __ldg(&g_RwT[f * 64 + r]),       0.0f);
                float h1 = fmaxf(bh[f + 1] + __ldg(&g_RwT[(f + 1) * 64 + r]), 0.0f);
                hidp[m] = pack2(h0, h1);
            }
            const ulonglong2* w2 = reinterpret_cast<const ulonglong2*>(sW2);
            float a = 0.0f;
            #pragma unroll
            for (int gb = 0; gb < 64; gb += 8) {
                float dp[8];
                #pragma unroll
                for (int u = 0; u < 8; u++) {
                    const int g = gb + u;
                    unsigned long long dpp = 0ull;
                    #pragma unroll
                    for (int j = 0; j < 8; j++) {
                        ulonglong2 wv = w2[g * 16 + j * 2 + fh];
                        dpp = fma2(wv.x, hidp[j * 2],     dpp);
                        dpp = fma2(wv.y, hidp[j * 2 + 1], dpp);
                    }
                    float2 dd = unpack2(dpp);
                    dp[u] = dd.x + dd.y;
                }
                #pragma unroll
                for (int u = 0; u < 8; u++)
                    dp[u] += __shfl_xor_sync(0xffffffffu, dp[u], 1);
                #pragma unroll
                for (int u = 0; u < 8; u++)
                    a += sw3[gb + u] * fmaxf(dp[u], 0.0f);
            }
            if (fh == 0) sA[task] = a;
        }
    }
    __syncthreads();

    // ====== exp(sigmoid(a)) tables =========================================
    if (tid < 96) {
        float e = __expf(1.0f / (1.0f + __expf(-sA[tid])));
        if (tid < 32) { sWk[tid] = e; sWks[tid] = e * sScale1[tid]; }
        else          sE2[tid - 32] = e;
    }
    __syncthreads();

    // ====== hop-2 gather with FUSED weights + denominator (all 4 warps) ====
    {
        float accx = 0.f, accy = 0.f, esum = 0.f;
        const float2* E2 = reinterpret_cast<const float2*>(E);
        const int pbase = warp * 256;
        #pragma unroll 8
        for (int t = 0; t < 256; t++) {
            int2  pr = sPair[pbase + t];     // single LDS.64 broadcast
            int  idx = pr.x & 0x1FFFF;
            float e  = sE2[pr.x >> 17];      // broadcast LDS, off the LDG path
            esum    += e;
            float wt = e * __int_as_float(pr.y);
            float2 v = E2[idx * 32 + lane];  // LDG.64 (L2-resident)
            accx += wt * v.x;
            accy += wt * v.y;
        }
        // broadcast reads -> every lane holds the full 256-pair esum already
        if (lane == 0) sDen[warp] = esum;
        // partials into this warp's own fully-consumed sPair segment
        sPair[pbase + lane] = make_int2(__float_as_int(accx), __float_as_int(accy));
    }
    __syncthreads();

    // ====== hop-1 agg (tid<64) + hop-2 combine (tid in [64,128)) ===========
    if (tid < 64) {
        float s1 = 0.f, acc = 0.f;
        #pragma unroll
        for (int k = 0; k < 32; k++) s1 += sWk[k];
        #pragma unroll 8
        for (int k = 0; k < 32; k++)
            acc += sWks[k] * E[sEnt1[k] * 64 + tid];
        sAgg1[tid] = acc / s1;
    } else {
        int f = tid - 64;
        int l = f >> 1, c = f & 1;
        float s2 = sDen[0] + sDen[1] + sDen[2] + sDen[3];
        float acc = 0.f;
        #pragma unroll
        for (int w = 0; w < 4; w++) {
            int2 pr = sPair[w * 256 + l];
            acc += __int_as_float(c ? pr.y : pr.x);
        }
        sAgg2[f] = acc / s2;
    }
    __syncthreads();

    // ====== v1/v2 = leaky(agg @ wx_w^T + wx_b) =============================
    if (tid < 64) {
        const float4* w = reinterpret_cast<const float4*>(wx_w + tid * 64);
        float a1 = wx_b[tid], a2 = a1;
        #pragma unroll
        for (int e4 = 0; e4 < 16; e4++) {
            float4 wv = w[e4];
            a1 += wv.x * sAgg1[e4*4]   + wv.y * sAgg1[e4*4+1]
                + wv.z * sAgg1[e4*4+2] + wv.w * sAgg1[e4*4+3];
            a2 += wv.x * sAgg2[e4*4]   + wv.y * sAgg2[e4*4+1]
                + wv.z * sAgg2[e4*4+2] + wv.w * sAgg2[e4*4+3];
        }
        sV1[tid] = (a1 >= 0.f) ? a1 : SLOPE * a1;
        sV2[tid] = (a2 >= 0.f) ? a2 : SLOPE * a2;
    }
    __syncthreads();

    // ====== emb1/emb2 = leaky([x, v] @ wc_w^T + wc_b) + h out ==============
    if (tid < 64) {
        const float4* w = reinterpret_cast<const float4*>(wc_w + tid * 128);
        float a1 = wc_b[tid], a2 = a1;
        #pragma unroll
        for (int e4 = 0; e4 < 16; e4++) {
            float4 wv = w[e4];
            a1 += wv.x * sh[e4*4]      + wv.y * sh[e4*4+1]
                + wv.z * sh[e4*4+2]    + wv.w * sh[e4*4+3];
            a2 += wv.x * shsum[e4*4]   + wv.y * shsum[e4*4+1]
                + wv.z * shsum[e4*4+2] + wv.w * shsum[e4*4+3];
        }
        #pragma unroll
        for (int e4 = 0; e4 < 16; e4++) {
            float4 wv = w[16 + e4];
            a1 += wv.x * sV1[e4*4]   + wv.y * sV1[e4*4+1]
                + wv.z * sV1[e4*4+2] + wv.w * sV1[e4*4+3];
            a2 += wv.x * sV2[e4*4]   + wv.y * sV2[e4*4+1]
                + wv.z * sV2[e4*4+2] + wv.w * sV2[e4*4+3];
        }
        out[b * 192 + 64 + tid]  = (a1 >= 0.f) ? a1 : SLOPE * a1;
        out[b * 192 + tid]       = (a2 >= 0.f) ? a2 : SLOPE * a2;
        out[b * 192 + 128 + tid] = sh[tid];
    }
}

extern "C" void kernel_launch(void* const* d_in, const int* in_sizes, int n_in,
                              void* d_out, int out_size) {
    const int*   entity_idx   = (const int*)  d_in[0];
    const int*   adj_entity   = (const int*)  d_in[1];
    const int*   adj_relation = (const int*)  d_in[2];
    const float* E            = (const float*)d_in[3];
    const float* R            = (const float*)d_in[4];
    const float* att_w1       = (const float*)d_in[5];
    const float* att_w2       = (const float*)d_in[6];
    const float* att_w3       = (const float*)d_in[7];
    const float* wx_w         = (const float*)d_in[8];
    const float* wx_b         = (const float*)d_in[9];
    const float* wc_w         = (const float*)d_in[10];
    const float* wc_b         = (const float*)d_in[11];
    float* out = (float*)d_out;

    prep_kernel<<<798, 256>>>(E, R, att_w1);
    kgan_main_kernel<<<BSZ, 128>>>(entity_idx, adj_entity, adj_relation, E,
                                   att_w1, att_w2, att_w3,
                                   wx_w, wx_b, wc_w, wc_b, out);
}